// round 16
// baseline (speedup 1.0000x reference)
#include <cuda_runtime.h>
#include <cstdint>

typedef unsigned long long u64;
typedef unsigned int u32;

#define BATCH 65536
#define NBLK 518
#define PACKF (NBLK * 48)          // 24864 floats (duplicated f32x2 weight pack)
#define OUT_STAB_OFF (BATCH * 180)
#define MAIN_CTAS 128
#define NGRP 6
#define MAIN_THREADS 384           // 6 groups x 2 warps, 64 slots/group

__device__ __align__(16) float g_wpack[PACKF];
__device__ __align__(16) float g_seed[BATCH * 3];
__device__ __align__(16) float g_S3[BATCH * 3];
__device__ __align__(16) float g_Mpart[3 * 540];   // 3 plain-store M slabs
__device__ u32 g_dpart[NBLK * MAIN_CTAS];   // per-CTA fixed-point diff partials

// ---------------- f32x2 helpers ----------------
__device__ __forceinline__ u64 pk2(float lo, float hi) {
    u64 r; asm("mov.b64 %0, {%1, %2};" : "=l"(r) : "f"(lo), "f"(hi)); return r;
}
__device__ __forceinline__ void upk2(u64 v, float& lo, float& hi) {
    asm("mov.b64 {%0, %1}, %2;" : "=f"(lo), "=f"(hi) : "l"(v));
}
__device__ __forceinline__ u64 fma2(u64 a, u64 b, u64 c) {
    u64 d; asm("fma.rn.f32x2 %0, %1, %2, %3;" : "=l"(d) : "l"(a), "l"(b), "l"(c)); return d;
}
__device__ __forceinline__ u64 add2(u64 a, u64 b) {
    u64 d; asm("add.rn.f32x2 %0, %1, %2;" : "=l"(d) : "l"(a), "l"(b)); return d;
}
__device__ __forceinline__ u64 abs2(u64 a) { return a & 0x7FFFFFFF7FFFFFFFull; }
__device__ __forceinline__ u64 tanh2(u64 v) {
    float a, b;
    asm("mov.b64 {%0, %1}, %2;" : "=f"(a), "=f"(b) : "l"(v));
    asm("tanh.approx.f32 %0, %0;" : "+f"(a));
    asm("tanh.approx.f32 %0, %0;" : "+f"(b));
    u64 r;
    asm("mov.b64 %0, {%1, %2};" : "=l"(r) : "f"(a), "f"(b));
    return r;
}
__device__ __forceinline__ float habs(u64 v) {   // |lo| + |hi|
    float a, b; upk2(v, a, b); return fabsf(a) + fabsf(b);
}
__device__ __forceinline__ void cp_async8(void* smem_dst, const void* gsrc) {
    u32 d = (u32)__cvta_generic_to_shared(smem_dst);
    asm volatile("cp.async.ca.shared.global [%0], [%1], 8;" :: "r"(d), "l"(gsrc) : "memory");
}
__device__ __forceinline__ void cp_async16(void* smem_dst, const void* gsrc) {
    u32 d = (u32)__cvta_generic_to_shared(smem_dst);
    asm volatile("cp.async.cg.shared.global [%0], [%1], 16;" :: "r"(d), "l"(gsrc) : "memory");
}
#define CP_ASYNC_WAIT() asm volatile("cp.async.commit_group;\ncp.async.wait_group 0;" ::: "memory")

// ---------------------------------------------------------------------------
// setup_kernel: 263 CTAs x 256 thr, self-contained (no cross-CTA deps).
//   CTAs 0..255  : seeds for 256 rows each (cp.async staging, all thr compute)
//   CTAs 256..259: weight pack quarters (each computes the 86 small rowsums)
//   CTAs 260..262: M slab partials (each computes its own 144 R3 rowsums)
// ---------------------------------------------------------------------------
#define SEED_CTAS 256
#define SETUP_SMEM (256 * 46 * 8 + 276 * 4)

__global__ void __launch_bounds__(256) setup_kernel(
    const float* __restrict__ x,  const float* __restrict__ Wl, const float* __restrict__ Wi,
    const float* __restrict__ R0, const float* __restrict__ R1,
    const float* __restrict__ R2, const float* __restrict__ R3,
    const float* __restrict__ Wf,
    const float* __restrict__ W1_0, const float* __restrict__ b1_0,
    const float* __restrict__ W2_0, const float* __restrict__ b2_0,
    const float* __restrict__ W1_1, const float* __restrict__ b1_1,
    const float* __restrict__ W2_1, const float* __restrict__ b2_1,
    const float* __restrict__ W1_2, const float* __restrict__ b1_2,
    const float* __restrict__ W2_2, const float* __restrict__ b2_2,
    const float* __restrict__ W1_3, const float* __restrict__ b1_3,
    const float* __restrict__ W2_3, const float* __restrict__ b2_3)
{
    extern __shared__ float2 s_x2[];
    const int tid = threadIdx.x;
    const int bid = blockIdx.x;

    if (bid < SEED_CTAS) {
        // ---- seeds: 256 rows per CTA, cp.async staging ----
        float* s_w = (float*)(s_x2 + 256 * 46);
        const int base = bid * 256;
        const float2* xg = (const float2*)(x + (size_t)base * 90);
        #pragma unroll 5
        for (int e = tid; e < 256 * 45; e += 256) {
            int r = e / 45;
            int k = e - r * 45;
            cp_async8(&s_x2[r * 46 + k], &xg[e]);
        }
        s_x2[tid * 46 + 45] = make_float2(0.f, 0.f);   // zero pad per row
        for (int i = tid; i < 138; i += 256) {
            float2 v = make_float2(0.f, 0.f);
            if (i < 135) v = ((const float2*)Wl)[i];
            ((float2*)s_w)[i] = v;
        }
        CP_ASYNC_WAIT();
        __syncthreads();

        const float4* xr  = (const float4*)s_x2 + tid * 23;   // 92 floats = 23 f4
        const float4* w4  = (const float4*)s_w;
        float L0 = 0.f, L1 = 0.f, L2 = 0.f;
        #pragma unroll
        for (int c = 0; c < 23; c++) {
            float4 xv = xr[c];
            float4 w0 = w4[3 * c], w1 = w4[3 * c + 1], w2 = w4[3 * c + 2];
            L0 = fmaf(xv.x, w0.x, L0); L1 = fmaf(xv.x, w0.y, L1); L2 = fmaf(xv.x, w0.z, L2);
            L0 = fmaf(xv.y, w0.w, L0); L1 = fmaf(xv.y, w1.x, L1); L2 = fmaf(xv.y, w1.y, L2);
            L0 = fmaf(xv.z, w1.z, L0); L1 = fmaf(xv.z, w1.w, L1); L2 = fmaf(xv.z, w2.x, L2);
            L0 = fmaf(xv.w, w2.y, L0); L1 = fmaf(xv.w, w2.z, L1); L2 = fmaf(xv.w, w2.w, L2);
        }
        const float C = 2.0943951023931953f;
        float E0 = __sinf(C * L0), E1 = __sinf(C * L1), E2 = __sinf(C * L2);
        float I0 = E0 * __ldg(&Wi[0]) + E1 * __ldg(&Wi[3]) + E2 * __ldg(&Wi[6]);
        float I1 = E0 * __ldg(&Wi[1]) + E1 * __ldg(&Wi[4]) + E2 * __ldg(&Wi[7]);
        float I2 = E0 * __ldg(&Wi[2]) + E1 * __ldg(&Wi[5]) + E2 * __ldg(&Wi[8]);
        const float TH = 1.0f / 3.0f;
        int row = base + tid;
        g_seed[row * 3 + 0] = (L0 + E0 + I0) * TH;
        g_seed[row * 3 + 1] = (L1 + E1 + I1) * TH;
        g_seed[row * 3 + 2] = (L2 + E2 + I2) * TH;
    } else if (bid < SEED_CTAS + 4) {
        // ---- weight pack quarter; compute the 86 small rowsums locally ----
        __shared__ float rs[86];
        int wid = tid >> 5, lane = tid & 31;
        for (int rr = wid; rr < 86; rr += 8) {
            const float* Rp; int n, row;
            if (rr < 2)       { Rp = R0; n = 2;  row = rr; }
            else if (rr < 14) { Rp = R1; n = 12; row = rr - 2; }
            else              { Rp = R2; n = 72; row = rr - 14; }
            float s = 0.f;
            for (int kk = lane; kk < n; kk += 32) s += Rp[row * n + kk];
            #pragma unroll
            for (int o = 16; o; o >>= 1) s += __shfl_xor_sync(0xffffffffu, s, o);
            if (lane == 0) rs[rr] = s;
        }
        __syncthreads();
        for (int e = (bid - SEED_CTAS) * 256 + tid; e < NBLK * 24; e += 4 * 256) {
            int blk = e / 24, k = e - blk * 24;
            int l, j;
            if (blk < 2)       { l = 0; j = blk; }
            else if (blk < 14) { l = 1; j = blk - 2; }
            else if (blk < 86) { l = 2; j = blk - 14; }
            else               { l = 3; j = blk - 86; }
            float c = 1.f;
            if (l == 1)      c = rs[0 + (j & 1)];
            else if (l == 2) c = rs[2 + (j % 12)];
            else if (l == 3) c = rs[14 + (j % 72)];
            const float *W1p, *B1p, *W2p, *B2p;
            if (l == 0)      { W1p = W1_0; B1p = b1_0; W2p = W2_0; B2p = b2_0; }
            else if (l == 1) { W1p = W1_1; B1p = b1_1; W2p = W2_1; B2p = b2_1; }
            else if (l == 2) { W1p = W1_2; B1p = b1_2; W2p = W2_2; B2p = b2_2; }
            else             { W1p = W1_3; B1p = b1_3; W2p = W2_3; B2p = b2_3; }
            float v;
            if (k < 9)       v = c * W1p[j * 9 + k];
            else if (k < 12) v = B1p[j * 3 + (k - 9)];
            else if (k < 21) v = W2p[j * 9 + (k - 12)];
            else             v = B2p[j * 3 + (k - 21)];
            g_wpack[2 * e]     = v;
            g_wpack[2 * e + 1] = v;
        }
    } else {
        // ---- M slab: own 144 R3 rowsums, then plain-store partial ----
        __shared__ float r3c[144];
        const int mb = bid - SEED_CTAS - 4;          // 0..2
        const int i0 = mb * 144;
        int wid = tid >> 5, lane = tid & 31;
        for (int rr = wid; rr < 144; rr += 8) {
            const float* Rp = R3 + (size_t)(i0 + rr) * 432;
            float s = 0.f;
            #pragma unroll 7
            for (int kk = lane; kk < 432; kk += 32) s += Rp[kk];
            #pragma unroll
            for (int o = 16; o; o >>= 1) s += __shfl_xor_sync(0xffffffffu, s, o);
            if (lane == 0) r3c[rr] = s;
        }
        __syncthreads();
        if (tid < 180) {
            float a0 = 0.f, a1 = 0.f, a2 = 0.f;
            const float* basep = Wf + (size_t)(3 * i0) * 180 + tid;
            #pragma unroll 4
            for (int ii = 0; ii < 144; ii++) {
                float rv = r3c[ii];
                a0 = fmaf(rv, __ldg(basep + (3 * ii + 0) * 180), a0);
                a1 = fmaf(rv, __ldg(basep + (3 * ii + 1) * 180), a1);
                a2 = fmaf(rv, __ldg(basep + (3 * ii + 2) * 180), a2);
            }
            g_Mpart[mb * 540 + 0 * 180 + tid] = a0;
            g_Mpart[mb * 540 + 1 * 180 + tid] = a1;
            g_Mpart[mb * 540 + 2 * 180 + tid] = a2;
        }
    }
}

// ---------------------------------------------------------------------------
// Main kernel: 128 CTAs x 384 thr (R12 config; hot loop untouched). SIX
// groups x 2 warps, 4 f32x2 pairs (8 rows)/thread, F-offload, rotated REDUX.
// Pack staged via cp.async (16B) — no LDG->STS register round-trip.
// ---------------------------------------------------------------------------
#define SLOTS 64
#define XSTRIDE (12 * SLOTS)              // 768 u64 per group
#define X_U64 (NGRP * XSTRIDE)            // 4608
#define P_U64 ((NGRP - 1) * XSTRIDE)      // 3840
#define F_U64 ((NGRP - 1) * XSTRIDE)      // 3840
#define MAIN_SMEM (PACKF * 4 + (X_U64 + P_U64 + F_U64) * 8 + NBLK * 2 * 4)

#define BLK4(W)                                                             \
    do {                                                                    \
        ulonglong2 q0=(W)[0],q1=(W)[1],q2=(W)[2],q3=(W)[3],q4=(W)[4],q5=(W)[5]; \
        ulonglong2 r0=(W)[6],r1=(W)[7],r2=(W)[8],r3=(W)[9],r4=(W)[10],r5=(W)[11]; \
        _Pragma("unroll")                                                   \
        for (int pp = 0; pp < 4; pp++) {                                    \
            u64 h0=fma2(S[3*pp],q0.x,fma2(S[3*pp+1],q1.y,fma2(S[3*pp+2],q3.x,q4.y))); \
            u64 h1=fma2(S[3*pp],q0.y,fma2(S[3*pp+1],q2.x,fma2(S[3*pp+2],q3.y,q5.x))); \
            u64 h2=fma2(S[3*pp],q1.x,fma2(S[3*pp+1],q2.y,fma2(S[3*pp+2],q4.x,q5.y))); \
            h0=tanh2(h0); h1=tanh2(h1); h2=tanh2(h2);                       \
            o[3*pp+0]=fma2(h0,r0.x,fma2(h1,r1.y,fma2(h2,r3.x,r4.y)));       \
            o[3*pp+1]=fma2(h0,r0.y,fma2(h1,r2.x,fma2(h2,r3.y,r5.x)));       \
            o[3*pp+2]=fma2(h0,r1.x,fma2(h1,r2.y,fma2(h2,r4.x,r5.y)));       \
        }                                                                   \
    } while (0)

#define DSQ4(dst)                                                           \
    do {                                                                    \
        u64 t0=add2(abs2(fma2(p[0], NEG1,o[0])), abs2(fma2(p[6], NEG1,o[6]))); \
        u64 t1=add2(abs2(fma2(p[1], NEG1,o[1])), abs2(fma2(p[7], NEG1,o[7]))); \
        u64 t2=add2(abs2(fma2(p[2], NEG1,o[2])), abs2(fma2(p[8], NEG1,o[8]))); \
        u64 t3=add2(abs2(fma2(p[3], NEG1,o[3])), abs2(fma2(p[9], NEG1,o[9]))); \
        u64 t4=add2(abs2(fma2(p[4], NEG1,o[4])), abs2(fma2(p[10],NEG1,o[10]))); \
        u64 t5=add2(abs2(fma2(p[5], NEG1,o[5])), abs2(fma2(p[11],NEG1,o[11]))); \
        u64 tt=add2(add2(add2(t0,t1),add2(t2,t3)),add2(t4,t5));             \
        dst = habs(tt) * 65536.0f;                                          \
    } while (0)

__global__ void __launch_bounds__(MAIN_THREADS, 1) main_kernel() {
    extern __shared__ u64 sw[];                      // weights: PACKF/2 u64
    u64* X = sw + PACKF / 2;                         // X_U64
    u64* P = X + X_U64;                              // P_U64
    u64* F = P + P_U64;                              // F_U64
    u32* sdiff = (u32*)(F + F_U64);                  // [NBLK][2]
    {
        const float4* src = (const float4*)g_wpack;
        float4* dst = (float4*)sw;
        for (int i = threadIdx.x; i < PACKF / 4; i += MAIN_THREADS)
            cp_async16(&dst[i], &src[i]);
        CP_ASYNC_WAIT();
    }
    __syncthreads();

    const int tid  = threadIdx.x;
    const int wid  = tid >> 5;
    const int lane = tid & 31;
    const int q    = wid >> 1;                       // group 0..5
    const int wg   = wid & 1;                        // warp within group
    const int slot = tid & 63;
    const bool l0  = (lane == 0);
    const int g = blockIdx.x * SLOTS + slot;         // rows 8g..8g+7

    u64 S[12], o[12];
    {
        const float4* sp = (const float4*)g_seed + 6 * g;
        float4 v0 = sp[0], v1 = sp[1], v2 = sp[2], v3 = sp[3], v4 = sp[4], v5 = sp[5];
        S[0] = pk2(v0.x, v0.w); S[1]  = pk2(v0.y, v1.x); S[2]  = pk2(v0.z, v1.y);
        S[3] = pk2(v1.z, v2.y); S[4]  = pk2(v1.w, v2.z); S[5]  = pk2(v2.x, v2.w);
        S[6] = pk2(v3.x, v3.w); S[7]  = pk2(v3.y, v4.x); S[8]  = pk2(v3.z, v4.y);
        S[9] = pk2(v4.z, v5.y); S[10] = pk2(v4.w, v5.z); S[11] = pk2(v5.x, v5.w);
    }

    const u64 NEG1 = 0xBF800000BF800000ull;
    u64 a[12], p[12];

    // ---- layer 0 (2 blocks, redundant on all groups, no exchange) ----
    {
        const ulonglong2* w2 = (const ulonglong2*)sw;
        BLK4(w2);
        #pragma unroll
        for (int c = 0; c < 12; c++) { a[c] = o[c]; p[c] = o[c]; }
        w2 += 12;
        BLK4(w2);
        #pragma unroll
        for (int c = 0; c < 12; c++) a[c] = add2(a[c], o[c]);
        float dsq;
        DSQ4(dsq);
        u32 fx = __float2uint_rn(dsq);
        fx = __reduce_add_sync(0xffffffffu, fx);
        if (q == 0 && l0) sdiff[1 * 2 + wg] = fx;
        #pragma unroll
        for (int c = 0; c < 12; c++) S[c] = a[c];
    }

    // ---- layers 1..3, six-way split, rotated diff reduction ----
    const u64* wl = sw + 2 * 24;
    int blkbase = 2;
    const int nbl3[3] = {12, 72, 432};

    #pragma unroll
    for (int l = 0; l < 3; l++) {
        const int n = nbl3[l];
        const int cnt = n / NGRP;
        const int s = q * cnt;
        const ulonglong2* w2 = (const ulonglong2*)(wl + s * 24);

        BLK4(w2);                                    // peeled first block
        #pragma unroll
        for (int c = 0; c < 12; c++) { a[c] = o[c]; p[c] = o[c]; }
        if (q >= 1) {                                // offload first-block outs
            u64* Fq = F + (q - 1) * XSTRIDE + slot;
            #pragma unroll
            for (int c = 0; c < 12; c++) Fq[c * SLOTS] = o[c];
        }
        w2 += 12;

        float dsq = 0.0f;                            // ds of previous iter
        u32* sdp = sdiff + (blkbase + s + 1) * 2 + wg;
        #pragma unroll 2
        for (int j = 1; j < cnt; j++) {
            // REDUX for iteration j-1 issues first (operands long ready)
            u32 fx = __float2uint_rn(dsq);
            fx = __reduce_add_sync(0xffffffffu, fx);
            BLK4(w2);                                // big independent chunk
            if (j >= 2) {                            // store diff of block s+j-1
                if (l0) *sdp = fx;
                sdp += 2;
            }
            #pragma unroll
            for (int c = 0; c < 12; c++) a[c] = add2(a[c], o[c]);
            DSQ4(dsq);                               // ds for THIS iter (j)
            #pragma unroll
            for (int c = 0; c < 12; c++) p[c] = o[c];
            w2 += 12;
        }
        {   // flush last diff (block s+cnt-1)
            u32 fx = __float2uint_rn(dsq);
            fx = __reduce_add_sync(0xffffffffu, fx);
            if (l0) *sdp = fx;
        }

        // ---- layer boundary: publish partials ----
        {
            u64* Xq = X + q * XSTRIDE + slot;
            #pragma unroll
            for (int c = 0; c < 12; c++) Xq[c * SLOTS] = a[c];
            if (q < NGRP - 1) {
                u64* Pq = P + q * XSTRIDE + slot;
                #pragma unroll
                for (int c = 0; c < 12; c++) Pq[c * SLOTS] = p[c];
            }
        }
        __syncthreads();
        {   // combine in FIXED order (identical across groups)
            const u64* X0 = X + slot;
            #pragma unroll
            for (int c = 0; c < 12; c++) {
                u64 v01 = add2(X0[c * SLOTS],               X0[XSTRIDE + c * SLOTS]);
                u64 v23 = add2(X0[2 * XSTRIDE + c * SLOTS], X0[3 * XSTRIDE + c * SLOTS]);
                u64 v45 = add2(X0[4 * XSTRIDE + c * SLOTS], X0[5 * XSTRIDE + c * SLOTS]);
                S[c] = add2(add2(v01, v23), v45);
            }
        }
        if (q >= 1) {   // boundary diff: my first block vs group q-1's last
            const u64* Pm = P + (q - 1) * XSTRIDE + slot;
            const u64* Fq = F + (q - 1) * XSTRIDE + slot;
            u64 t0 = add2(abs2(fma2(Pm[0],         NEG1, Fq[0])),
                          abs2(fma2(Pm[6 * SLOTS], NEG1, Fq[6 * SLOTS])));
            u64 t1 = add2(abs2(fma2(Pm[1 * SLOTS], NEG1, Fq[1 * SLOTS])),
                          abs2(fma2(Pm[7 * SLOTS], NEG1, Fq[7 * SLOTS])));
            u64 t2 = add2(abs2(fma2(Pm[2 * SLOTS], NEG1, Fq[2 * SLOTS])),
                          abs2(fma2(Pm[8 * SLOTS], NEG1, Fq[8 * SLOTS])));
            u64 t3 = add2(abs2(fma2(Pm[3 * SLOTS], NEG1, Fq[3 * SLOTS])),
                          abs2(fma2(Pm[9 * SLOTS], NEG1, Fq[9 * SLOTS])));
            u64 t4 = add2(abs2(fma2(Pm[4 * SLOTS], NEG1, Fq[4 * SLOTS])),
                          abs2(fma2(Pm[10 * SLOTS], NEG1, Fq[10 * SLOTS])));
            u64 t5 = add2(abs2(fma2(Pm[5 * SLOTS], NEG1, Fq[5 * SLOTS])),
                          abs2(fma2(Pm[11 * SLOTS], NEG1, Fq[11 * SLOTS])));
            u64 tt = add2(add2(add2(t0, t1), add2(t2, t3)), add2(t4, t5));
            u32 fx = __float2uint_rn(habs(tt) * 65536.0f);
            fx = __reduce_add_sync(0xffffffffu, fx);
            if (l0) sdiff[(blkbase + s) * 2 + wg] = fx;
        }
        __syncthreads();                             // protect X/P/F reuse
        blkbase += n;
        wl += n * 24;
    }

    // S3 write (all groups hold identical final S; group 0 writes)
    if (q == 0) {
        float a0l, a0h, a1l, a1h, a2l, a2h, b0l, b0h, b1l, b1h, b2l, b2h;
        float4* op = (float4*)g_S3 + 6 * g;
        upk2(S[0], a0l, a0h); upk2(S[1], a1l, a1h); upk2(S[2], a2l, a2h);
        upk2(S[3], b0l, b0h); upk2(S[4], b1l, b1h); upk2(S[5], b2l, b2h);
        op[0] = make_float4(a0l, a1l, a2l, a0h);
        op[1] = make_float4(a1h, a2h, b0l, b1l);
        op[2] = make_float4(b2l, b0h, b1h, b2h);
        upk2(S[6], a0l, a0h); upk2(S[7],  a1l, a1h); upk2(S[8],  a2l, a2h);
        upk2(S[9], b0l, b0h); upk2(S[10], b1l, b1h); upk2(S[11], b2l, b2h);
        op[3] = make_float4(a0l, a1l, a2l, a0h);
        op[4] = make_float4(a1h, a2h, b0l, b1l);
        op[5] = make_float4(b2l, b0h, b1h, b2h);
    }

    // export per-CTA diff partials
    __syncthreads();
    for (int d = tid; d < NBLK; d += MAIN_THREADS) {
        u32 s2 = sdiff[d * 2 + 0] + sdiff[d * 2 + 1];
        g_dpart[d * MAIN_CTAS + blockIdx.x] = s2;
    }
}

// ---------------------------------------------------------------------------
// Epilogue: 2048 CTAs x 192 thr, 32 rows/CTA. Thread owns one c-column,
// summing M from the 3 slabs (L2-resident). First 87 CTAs emit stab outputs.
// ---------------------------------------------------------------------------
__global__ void __launch_bounds__(192) out_kernel(const float* __restrict__ bfin,
                                                  float* __restrict__ out) {
    __shared__ __align__(16) float s_s3[96];         // 32 rows x 3
    const int t = threadIdx.x;

    if (t < 24)
        ((float4*)s_s3)[t] = __ldg((const float4*)(g_S3 + (size_t)blockIdx.x * 96) + t);

    // ---- stability outputs ----
    const int gw = blockIdx.x * 6 + (t >> 5);
    if (blockIdx.x < 87 && gw < NBLK) {
        const int lane = t & 31;
        u64 s = 0;
        #pragma unroll
        for (int k = 0; k < 4; k++)
            s += (u64)__ldg(&g_dpart[gw * MAIN_CTAS + lane + k * 32]);
        #pragma unroll
        for (int o = 16; o; o >>= 1) s += __shfl_xor_sync(0xffffffffu, s, o);
        if (lane == 0) {
            bool first = (gw == 0) | (gw == 2) | (gw == 14) | (gw == 86);
            float val = 1.0f;
            if (!first) {
                double mean = (double)s * (1.0 / (65536.0 * 65536.0 * 3.0));
                double v = 1.0 - mean;
                val = (float)(v > 0.0 ? v : 0.0);
            }
            out[OUT_STAB_OFF + gw] = val;
        }
    }

    const int c  = t % 48;
    const int rg = t / 48;                 // 0..3
    const bool act = (c < 45);
    float4 m0 = make_float4(0.f, 0.f, 0.f, 0.f);
    float4 m1 = m0, m2 = m0, b4 = m0;
    if (act) {
        #pragma unroll
        for (int k = 0; k < 3; k++) {
            const float* Mp = g_Mpart + k * 540;
            float4 u0 = __ldg((const float4*)(Mp) + c);
            float4 u1 = __ldg((const float4*)(Mp + 180) + c);
            float4 u2 = __ldg((const float4*)(Mp + 360) + c);
            m0.x += u0.x; m0.y += u0.y; m0.z += u0.z; m0.w += u0.w;
            m1.x += u1.x; m1.y += u1.y; m1.z += u1.z; m1.w += u1.w;
            m2.x += u2.x; m2.y += u2.y; m2.z += u2.z; m2.w += u2.w;
        }
        b4 = __ldg((const float4*)bfin + c);
    }
    __syncthreads();
    const int base = rg * 8;
    #pragma unroll
    for (int it = 0; it < 8; it++) {
        int r = base + it;
        float s0 = s_s3[r * 3 + 0];
        float s1 = s_s3[r * 3 + 1];
        float s2 = s_s3[r * 3 + 2];
        if (act) {
            float4 o4;
            o4.x = fmaf(s0, m0.x, fmaf(s1, m1.x, fmaf(s2, m2.x, b4.x)));
            o4.y = fmaf(s0, m0.y, fmaf(s1, m1.y, fmaf(s2, m2.y, b4.y)));
            o4.z = fmaf(s0, m0.z, fmaf(s1, m1.z, fmaf(s2, m2.z, b4.z)));
            o4.w = fmaf(s0, m0.w, fmaf(s1, m1.w, fmaf(s2, m2.w, b4.w)));
            ((float4*)out)[((size_t)blockIdx.x * 32 + r) * 45 + c] = o4;
        }
    }
}

extern "C" void kernel_launch(void* const* d_in, const int* in_sizes, int n_in,
                              void* d_out, int out_size) {
    const float* x    = (const float*)d_in[0];
    const float* Wl   = (const float*)d_in[1];
    const float* Wi   = (const float*)d_in[2];
    const float* W1_0 = (const float*)d_in[3];
    const float* b1_0 = (const float*)d_in[4];
    const float* W2_0 = (const float*)d_in[5];
    const float* b2_0 = (const float*)d_in[6];
    const float* R0   = (const float*)d_in[7];
    const float* W1_1 = (const float*)d_in[8];
    const float* b1_1 = (const float*)d_in[9];
    const float* W2_1 = (const float*)d_in[10];
    const float* b2_1 = (const float*)d_in[11];
    const float* R1   = (const float*)d_in[12];
    const float* W1_2 = (const float*)d_in[13];
    const float* b1_2 = (const float*)d_in[14];
    const float* W2_2 = (const float*)d_in[15];
    const float* b2_2 = (const float*)d_in[16];
    const float* R2   = (const float*)d_in[17];
    const float* W1_3 = (const float*)d_in[18];
    const float* b1_3 = (const float*)d_in[19];
    const float* W2_3 = (const float*)d_in[20];
    const float* b2_3 = (const float*)d_in[21];
    const float* R3   = (const float*)d_in[22];
    const float* Wf   = (const float*)d_in[23];
    const float* bf   = (const float*)d_in[24];

    cudaFuncSetAttribute(setup_kernel, cudaFuncAttributeMaxDynamicSharedMemorySize, SETUP_SMEM);
    cudaFuncSetAttribute(main_kernel, cudaFuncAttributeMaxDynamicSharedMemorySize, MAIN_SMEM);

    setup_kernel<<<SEED_CTAS + 7, 256, SETUP_SMEM>>>(
        x, Wl, Wi, R0, R1, R2, R3, Wf,
        W1_0, b1_0, W2_0, b2_0,
        W1_1, b1_1, W2_1, b2_1,
        W1_2, b1_2, W2_2, b2_2,
        W1_3, b1_3, W2_3, b2_3);
    main_kernel<<<MAIN_CTAS, MAIN_THREADS, MAIN_SMEM>>>();
    out_kernel<<<2048, 192>>>(bf, (float*)d_out);
}

// round 17
// speedup vs baseline: 1.2484x; 1.2484x over previous
#include <cuda_runtime.h>
#include <cstdint>

typedef unsigned long long u64;
typedef unsigned int u32;

#define BATCH 65536
#define NBLK 518
#define PACKF (NBLK * 48)          // 24864 floats (duplicated f32x2 weight pack)
#define OUT_STAB_OFF (BATCH * 180)
#define MAIN_CTAS 128
#define NGRP 6
#define MAIN_THREADS 384           // 6 groups x 2 warps, 64 slots/group

__device__ __align__(16) float g_wpack[PACKF];
__device__ __align__(16) float g_seed[BATCH * 3];
__device__ __align__(16) float g_S3[BATCH * 3];
__device__ __align__(16) float g_Mpart[9 * 540];   // 9 plain-store M slabs
__device__ u32 g_dpart[NBLK * MAIN_CTAS];   // per-CTA fixed-point diff partials

// ---------------- f32x2 helpers ----------------
__device__ __forceinline__ u64 pk2(float lo, float hi) {
    u64 r; asm("mov.b64 %0, {%1, %2};" : "=l"(r) : "f"(lo), "f"(hi)); return r;
}
__device__ __forceinline__ void upk2(u64 v, float& lo, float& hi) {
    asm("mov.b64 {%0, %1}, %2;" : "=f"(lo), "=f"(hi) : "l"(v));
}
__device__ __forceinline__ u64 fma2(u64 a, u64 b, u64 c) {
    u64 d; asm("fma.rn.f32x2 %0, %1, %2, %3;" : "=l"(d) : "l"(a), "l"(b), "l"(c)); return d;
}
__device__ __forceinline__ u64 add2(u64 a, u64 b) {
    u64 d; asm("add.rn.f32x2 %0, %1, %2;" : "=l"(d) : "l"(a), "l"(b)); return d;
}
__device__ __forceinline__ u64 abs2(u64 a) { return a & 0x7FFFFFFF7FFFFFFFull; }
__device__ __forceinline__ u64 tanh2(u64 v) {
    float a, b;
    asm("mov.b64 {%0, %1}, %2;" : "=f"(a), "=f"(b) : "l"(v));
    asm("tanh.approx.f32 %0, %0;" : "+f"(a));
    asm("tanh.approx.f32 %0, %0;" : "+f"(b));
    u64 r;
    asm("mov.b64 %0, {%1, %2};" : "=l"(r) : "f"(a), "f"(b));
    return r;
}
__device__ __forceinline__ float habs(u64 v) {   // |lo| + |hi|
    float a, b; upk2(v, a, b); return fabsf(a) + fabsf(b);
}
__device__ __forceinline__ void cp_async8(void* smem_dst, const void* gsrc) {
    u32 d = (u32)__cvta_generic_to_shared(smem_dst);
    asm volatile("cp.async.ca.shared.global [%0], [%1], 8;" :: "r"(d), "l"(gsrc) : "memory");
}
__device__ __forceinline__ void cp_async16(void* smem_dst, const void* gsrc) {
    u32 d = (u32)__cvta_generic_to_shared(smem_dst);
    asm volatile("cp.async.cg.shared.global [%0], [%1], 16;" :: "r"(d), "l"(gsrc) : "memory");
}
#define CP_ASYNC_WAIT() asm volatile("cp.async.commit_group;\ncp.async.wait_group 0;" ::: "memory")

// ---------------------------------------------------------------------------
// setup_kernel: 269 CTAs x 256 thr, self-contained (no cross-CTA deps).
//   CTAs 0..255  : seeds for 256 rows each (cp.async staging, all thr compute)
//   CTAs 256..259: weight pack quarters (each computes the 86 small rowsums)
//   CTAs 260..268: M slab partials (each computes its own 48 R3 rowsums)
// ---------------------------------------------------------------------------
#define SEED_CTAS 256
#define SETUP_SMEM (256 * 46 * 8 + 276 * 4)

__global__ void __launch_bounds__(256) setup_kernel(
    const float* __restrict__ x,  const float* __restrict__ Wl, const float* __restrict__ Wi,
    const float* __restrict__ R0, const float* __restrict__ R1,
    const float* __restrict__ R2, const float* __restrict__ R3,
    const float* __restrict__ Wf,
    const float* __restrict__ W1_0, const float* __restrict__ b1_0,
    const float* __restrict__ W2_0, const float* __restrict__ b2_0,
    const float* __restrict__ W1_1, const float* __restrict__ b1_1,
    const float* __restrict__ W2_1, const float* __restrict__ b2_1,
    const float* __restrict__ W1_2, const float* __restrict__ b1_2,
    const float* __restrict__ W2_2, const float* __restrict__ b2_2,
    const float* __restrict__ W1_3, const float* __restrict__ b1_3,
    const float* __restrict__ W2_3, const float* __restrict__ b2_3)
{
    extern __shared__ float2 s_x2[];
    const int tid = threadIdx.x;
    const int bid = blockIdx.x;

    if (bid < SEED_CTAS) {
        // ---- seeds: 256 rows per CTA, cp.async staging ----
        float* s_w = (float*)(s_x2 + 256 * 46);
        const int base = bid * 256;
        const float2* xg = (const float2*)(x + (size_t)base * 90);
        #pragma unroll 5
        for (int e = tid; e < 256 * 45; e += 256) {
            int r = e / 45;
            int k = e - r * 45;
            cp_async8(&s_x2[r * 46 + k], &xg[e]);
        }
        s_x2[tid * 46 + 45] = make_float2(0.f, 0.f);   // zero pad per row
        for (int i = tid; i < 138; i += 256) {
            float2 v = make_float2(0.f, 0.f);
            if (i < 135) v = ((const float2*)Wl)[i];
            ((float2*)s_w)[i] = v;
        }
        CP_ASYNC_WAIT();
        __syncthreads();

        const float4* xr  = (const float4*)s_x2 + tid * 23;   // 92 floats = 23 f4
        const float4* w4  = (const float4*)s_w;
        float L0 = 0.f, L1 = 0.f, L2 = 0.f;
        #pragma unroll
        for (int c = 0; c < 23; c++) {
            float4 xv = xr[c];
            float4 w0 = w4[3 * c], w1 = w4[3 * c + 1], w2 = w4[3 * c + 2];
            L0 = fmaf(xv.x, w0.x, L0); L1 = fmaf(xv.x, w0.y, L1); L2 = fmaf(xv.x, w0.z, L2);
            L0 = fmaf(xv.y, w0.w, L0); L1 = fmaf(xv.y, w1.x, L1); L2 = fmaf(xv.y, w1.y, L2);
            L0 = fmaf(xv.z, w1.z, L0); L1 = fmaf(xv.z, w1.w, L1); L2 = fmaf(xv.z, w2.x, L2);
            L0 = fmaf(xv.w, w2.y, L0); L1 = fmaf(xv.w, w2.z, L1); L2 = fmaf(xv.w, w2.w, L2);
        }
        const float C = 2.0943951023931953f;
        float E0 = __sinf(C * L0), E1 = __sinf(C * L1), E2 = __sinf(C * L2);
        float I0 = E0 * __ldg(&Wi[0]) + E1 * __ldg(&Wi[3]) + E2 * __ldg(&Wi[6]);
        float I1 = E0 * __ldg(&Wi[1]) + E1 * __ldg(&Wi[4]) + E2 * __ldg(&Wi[7]);
        float I2 = E0 * __ldg(&Wi[2]) + E1 * __ldg(&Wi[5]) + E2 * __ldg(&Wi[8]);
        const float TH = 1.0f / 3.0f;
        int row = base + tid;
        g_seed[row * 3 + 0] = (L0 + E0 + I0) * TH;
        g_seed[row * 3 + 1] = (L1 + E1 + I1) * TH;
        g_seed[row * 3 + 2] = (L2 + E2 + I2) * TH;
    } else if (bid < SEED_CTAS + 4) {
        // ---- weight pack quarter; compute the 86 small rowsums locally ----
        __shared__ float rs[86];
        int wid = tid >> 5, lane = tid & 31;
        for (int rr = wid; rr < 86; rr += 8) {
            const float* Rp; int n, row;
            if (rr < 2)       { Rp = R0; n = 2;  row = rr; }
            else if (rr < 14) { Rp = R1; n = 12; row = rr - 2; }
            else              { Rp = R2; n = 72; row = rr - 14; }
            float s = 0.f;
            for (int kk = lane; kk < n; kk += 32) s += Rp[row * n + kk];
            #pragma unroll
            for (int o = 16; o; o >>= 1) s += __shfl_xor_sync(0xffffffffu, s, o);
            if (lane == 0) rs[rr] = s;
        }
        __syncthreads();
        for (int e = (bid - SEED_CTAS) * 256 + tid; e < NBLK * 24; e += 4 * 256) {
            int blk = e / 24, k = e - blk * 24;
            int l, j;
            if (blk < 2)       { l = 0; j = blk; }
            else if (blk < 14) { l = 1; j = blk - 2; }
            else if (blk < 86) { l = 2; j = blk - 14; }
            else               { l = 3; j = blk - 86; }
            float c = 1.f;
            if (l == 1)      c = rs[0 + (j & 1)];
            else if (l == 2) c = rs[2 + (j % 12)];
            else if (l == 3) c = rs[14 + (j % 72)];
            const float *W1p, *B1p, *W2p, *B2p;
            if (l == 0)      { W1p = W1_0; B1p = b1_0; W2p = W2_0; B2p = b2_0; }
            else if (l == 1) { W1p = W1_1; B1p = b1_1; W2p = W2_1; B2p = b2_1; }
            else if (l == 2) { W1p = W1_2; B1p = b1_2; W2p = W2_2; B2p = b2_2; }
            else             { W1p = W1_3; B1p = b1_3; W2p = W2_3; B2p = b2_3; }
            float v;
            if (k < 9)       v = c * W1p[j * 9 + k];
            else if (k < 12) v = B1p[j * 3 + (k - 9)];
            else if (k < 21) v = W2p[j * 9 + (k - 12)];
            else             v = B2p[j * 3 + (k - 21)];
            g_wpack[2 * e]     = v;
            g_wpack[2 * e + 1] = v;
        }
    } else {
        // ---- M slab: own 48 R3 rowsums, then plain-store partial ----
        __shared__ float r3c[48];
        const int mb = bid - SEED_CTAS - 4;          // 0..8
        const int i0 = mb * 48;
        int wid = tid >> 5, lane = tid & 31;
        for (int rr = wid; rr < 48; rr += 8) {
            const float* Rp = R3 + (size_t)(i0 + rr) * 432;
            float s = 0.f;
            #pragma unroll 7
            for (int kk = lane; kk < 432; kk += 32) s += Rp[kk];
            #pragma unroll
            for (int o = 16; o; o >>= 1) s += __shfl_xor_sync(0xffffffffu, s, o);
            if (lane == 0) r3c[rr] = s;
        }
        __syncthreads();
        if (tid < 180) {
            float a0 = 0.f, a1 = 0.f, a2 = 0.f;
            const float* basep = Wf + (size_t)(3 * i0) * 180 + tid;
            #pragma unroll 4
            for (int ii = 0; ii < 48; ii++) {
                float rv = r3c[ii];
                a0 = fmaf(rv, __ldg(basep + (3 * ii + 0) * 180), a0);
                a1 = fmaf(rv, __ldg(basep + (3 * ii + 1) * 180), a1);
                a2 = fmaf(rv, __ldg(basep + (3 * ii + 2) * 180), a2);
            }
            g_Mpart[mb * 540 + 0 * 180 + tid] = a0;
            g_Mpart[mb * 540 + 1 * 180 + tid] = a1;
            g_Mpart[mb * 540 + 2 * 180 + tid] = a2;
        }
    }
}

// ---------------------------------------------------------------------------
// Main kernel: 128 CTAs x 384 thr (R12 config; hot loop untouched). SIX
// groups x 2 warps, 4 f32x2 pairs (8 rows)/thread, F-offload, rotated REDUX.
// Pack staged via cp.async (16B) — no LDG->STS register round-trip.
// ---------------------------------------------------------------------------
#define SLOTS 64
#define XSTRIDE (12 * SLOTS)              // 768 u64 per group
#define X_U64 (NGRP * XSTRIDE)            // 4608
#define P_U64 ((NGRP - 1) * XSTRIDE)      // 3840
#define F_U64 ((NGRP - 1) * XSTRIDE)      // 3840
#define MAIN_SMEM (PACKF * 4 + (X_U64 + P_U64 + F_U64) * 8 + NBLK * 2 * 4)

#define BLK4(W)                                                             \
    do {                                                                    \
        ulonglong2 q0=(W)[0],q1=(W)[1],q2=(W)[2],q3=(W)[3],q4=(W)[4],q5=(W)[5]; \
        ulonglong2 r0=(W)[6],r1=(W)[7],r2=(W)[8],r3=(W)[9],r4=(W)[10],r5=(W)[11]; \
        _Pragma("unroll")                                                   \
        for (int pp = 0; pp < 4; pp++) {                                    \
            u64 h0=fma2(S[3*pp],q0.x,fma2(S[3*pp+1],q1.y,fma2(S[3*pp+2],q3.x,q4.y))); \
            u64 h1=fma2(S[3*pp],q0.y,fma2(S[3*pp+1],q2.x,fma2(S[3*pp+2],q3.y,q5.x))); \
            u64 h2=fma2(S[3*pp],q1.x,fma2(S[3*pp+1],q2.y,fma2(S[3*pp+2],q4.x,q5.y))); \
            h0=tanh2(h0); h1=tanh2(h1); h2=tanh2(h2);                       \
            o[3*pp+0]=fma2(h0,r0.x,fma2(h1,r1.y,fma2(h2,r3.x,r4.y)));       \
            o[3*pp+1]=fma2(h0,r0.y,fma2(h1,r2.x,fma2(h2,r3.y,r5.x)));       \
            o[3*pp+2]=fma2(h0,r1.x,fma2(h1,r2.y,fma2(h2,r4.x,r5.y)));       \
        }                                                                   \
    } while (0)

#define DSQ4(dst)                                                           \
    do {                                                                    \
        u64 t0=add2(abs2(fma2(p[0], NEG1,o[0])), abs2(fma2(p[6], NEG1,o[6]))); \
        u64 t1=add2(abs2(fma2(p[1], NEG1,o[1])), abs2(fma2(p[7], NEG1,o[7]))); \
        u64 t2=add2(abs2(fma2(p[2], NEG1,o[2])), abs2(fma2(p[8], NEG1,o[8]))); \
        u64 t3=add2(abs2(fma2(p[3], NEG1,o[3])), abs2(fma2(p[9], NEG1,o[9]))); \
        u64 t4=add2(abs2(fma2(p[4], NEG1,o[4])), abs2(fma2(p[10],NEG1,o[10]))); \
        u64 t5=add2(abs2(fma2(p[5], NEG1,o[5])), abs2(fma2(p[11],NEG1,o[11]))); \
        u64 tt=add2(add2(add2(t0,t1),add2(t2,t3)),add2(t4,t5));             \
        dst = habs(tt) * 65536.0f;                                          \
    } while (0)

__global__ void __launch_bounds__(MAIN_THREADS, 1) main_kernel() {
    extern __shared__ u64 sw[];                      // weights: PACKF/2 u64
    u64* X = sw + PACKF / 2;                         // X_U64
    u64* P = X + X_U64;                              // P_U64
    u64* F = P + P_U64;                              // F_U64
    u32* sdiff = (u32*)(F + F_U64);                  // [NBLK][2]
    {
        const float4* src = (const float4*)g_wpack;
        float4* dst = (float4*)sw;
        for (int i = threadIdx.x; i < PACKF / 4; i += MAIN_THREADS)
            cp_async16(&dst[i], &src[i]);
        CP_ASYNC_WAIT();
    }
    __syncthreads();

    const int tid  = threadIdx.x;
    const int wid  = tid >> 5;
    const int lane = tid & 31;
    const int q    = wid >> 1;                       // group 0..5
    const int wg   = wid & 1;                        // warp within group
    const int slot = tid & 63;
    const bool l0  = (lane == 0);
    const int g = blockIdx.x * SLOTS + slot;         // rows 8g..8g+7

    u64 S[12], o[12];
    {
        const float4* sp = (const float4*)g_seed + 6 * g;
        float4 v0 = sp[0], v1 = sp[1], v2 = sp[2], v3 = sp[3], v4 = sp[4], v5 = sp[5];
        S[0] = pk2(v0.x, v0.w); S[1]  = pk2(v0.y, v1.x); S[2]  = pk2(v0.z, v1.y);
        S[3] = pk2(v1.z, v2.y); S[4]  = pk2(v1.w, v2.z); S[5]  = pk2(v2.x, v2.w);
        S[6] = pk2(v3.x, v3.w); S[7]  = pk2(v3.y, v4.x); S[8]  = pk2(v3.z, v4.y);
        S[9] = pk2(v4.z, v5.y); S[10] = pk2(v4.w, v5.z); S[11] = pk2(v5.x, v5.w);
    }

    const u64 NEG1 = 0xBF800000BF800000ull;
    u64 a[12], p[12];

    // ---- layer 0 (2 blocks, redundant on all groups, no exchange) ----
    {
        const ulonglong2* w2 = (const ulonglong2*)sw;
        BLK4(w2);
        #pragma unroll
        for (int c = 0; c < 12; c++) { a[c] = o[c]; p[c] = o[c]; }
        w2 += 12;
        BLK4(w2);
        #pragma unroll
        for (int c = 0; c < 12; c++) a[c] = add2(a[c], o[c]);
        float dsq;
        DSQ4(dsq);
        u32 fx = __float2uint_rn(dsq);
        fx = __reduce_add_sync(0xffffffffu, fx);
        if (q == 0 && l0) sdiff[1 * 2 + wg] = fx;
        #pragma unroll
        for (int c = 0; c < 12; c++) S[c] = a[c];
    }

    // ---- layers 1..3, six-way split, rotated diff reduction ----
    const u64* wl = sw + 2 * 24;
    int blkbase = 2;
    const int nbl3[3] = {12, 72, 432};

    #pragma unroll
    for (int l = 0; l < 3; l++) {
        const int n = nbl3[l];
        const int cnt = n / NGRP;
        const int s = q * cnt;
        const ulonglong2* w2 = (const ulonglong2*)(wl + s * 24);

        BLK4(w2);                                    // peeled first block
        #pragma unroll
        for (int c = 0; c < 12; c++) { a[c] = o[c]; p[c] = o[c]; }
        if (q >= 1) {                                // offload first-block outs
            u64* Fq = F + (q - 1) * XSTRIDE + slot;
            #pragma unroll
            for (int c = 0; c < 12; c++) Fq[c * SLOTS] = o[c];
        }
        w2 += 12;

        float dsq = 0.0f;                            // ds of previous iter
        u32* sdp = sdiff + (blkbase + s + 1) * 2 + wg;
        #pragma unroll 2
        for (int j = 1; j < cnt; j++) {
            // REDUX for iteration j-1 issues first (operands long ready)
            u32 fx = __float2uint_rn(dsq);
            fx = __reduce_add_sync(0xffffffffu, fx);
            BLK4(w2);                                // big independent chunk
            if (j >= 2) {                            // store diff of block s+j-1
                if (l0) *sdp = fx;
                sdp += 2;
            }
            #pragma unroll
            for (int c = 0; c < 12; c++) a[c] = add2(a[c], o[c]);
            DSQ4(dsq);                               // ds for THIS iter (j)
            #pragma unroll
            for (int c = 0; c < 12; c++) p[c] = o[c];
            w2 += 12;
        }
        {   // flush last diff (block s+cnt-1)
            u32 fx = __float2uint_rn(dsq);
            fx = __reduce_add_sync(0xffffffffu, fx);
            if (l0) *sdp = fx;
        }

        // ---- layer boundary: publish partials ----
        {
            u64* Xq = X + q * XSTRIDE + slot;
            #pragma unroll
            for (int c = 0; c < 12; c++) Xq[c * SLOTS] = a[c];
            if (q < NGRP - 1) {
                u64* Pq = P + q * XSTRIDE + slot;
                #pragma unroll
                for (int c = 0; c < 12; c++) Pq[c * SLOTS] = p[c];
            }
        }
        __syncthreads();
        {   // combine in FIXED order (identical across groups)
            const u64* X0 = X + slot;
            #pragma unroll
            for (int c = 0; c < 12; c++) {
                u64 v01 = add2(X0[c * SLOTS],               X0[XSTRIDE + c * SLOTS]);
                u64 v23 = add2(X0[2 * XSTRIDE + c * SLOTS], X0[3 * XSTRIDE + c * SLOTS]);
                u64 v45 = add2(X0[4 * XSTRIDE + c * SLOTS], X0[5 * XSTRIDE + c * SLOTS]);
                S[c] = add2(add2(v01, v23), v45);
            }
        }
        if (q >= 1) {   // boundary diff: my first block vs group q-1's last
            const u64* Pm = P + (q - 1) * XSTRIDE + slot;
            const u64* Fq = F + (q - 1) * XSTRIDE + slot;
            u64 t0 = add2(abs2(fma2(Pm[0],         NEG1, Fq[0])),
                          abs2(fma2(Pm[6 * SLOTS], NEG1, Fq[6 * SLOTS])));
            u64 t1 = add2(abs2(fma2(Pm[1 * SLOTS], NEG1, Fq[1 * SLOTS])),
                          abs2(fma2(Pm[7 * SLOTS], NEG1, Fq[7 * SLOTS])));
            u64 t2 = add2(abs2(fma2(Pm[2 * SLOTS], NEG1, Fq[2 * SLOTS])),
                          abs2(fma2(Pm[8 * SLOTS], NEG1, Fq[8 * SLOTS])));
            u64 t3 = add2(abs2(fma2(Pm[3 * SLOTS], NEG1, Fq[3 * SLOTS])),
                          abs2(fma2(Pm[9 * SLOTS], NEG1, Fq[9 * SLOTS])));
            u64 t4 = add2(abs2(fma2(Pm[4 * SLOTS], NEG1, Fq[4 * SLOTS])),
                          abs2(fma2(Pm[10 * SLOTS], NEG1, Fq[10 * SLOTS])));
            u64 t5 = add2(abs2(fma2(Pm[5 * SLOTS], NEG1, Fq[5 * SLOTS])),
                          abs2(fma2(Pm[11 * SLOTS], NEG1, Fq[11 * SLOTS])));
            u64 tt = add2(add2(add2(t0, t1), add2(t2, t3)), add2(t4, t5));
            u32 fx = __float2uint_rn(habs(tt) * 65536.0f);
            fx = __reduce_add_sync(0xffffffffu, fx);
            if (l0) sdiff[(blkbase + s) * 2 + wg] = fx;
        }
        __syncthreads();                             // protect X/P/F reuse
        blkbase += n;
        wl += n * 24;
    }

    // S3 write (all groups hold identical final S; group 0 writes)
    if (q == 0) {
        float a0l, a0h, a1l, a1h, a2l, a2h, b0l, b0h, b1l, b1h, b2l, b2h;
        float4* op = (float4*)g_S3 + 6 * g;
        upk2(S[0], a0l, a0h); upk2(S[1], a1l, a1h); upk2(S[2], a2l, a2h);
        upk2(S[3], b0l, b0h); upk2(S[4], b1l, b1h); upk2(S[5], b2l, b2h);
        op[0] = make_float4(a0l, a1l, a2l, a0h);
        op[1] = make_float4(a1h, a2h, b0l, b1l);
        op[2] = make_float4(b2l, b0h, b1h, b2h);
        upk2(S[6], a0l, a0h); upk2(S[7],  a1l, a1h); upk2(S[8],  a2l, a2h);
        upk2(S[9], b0l, b0h); upk2(S[10], b1l, b1h); upk2(S[11], b2l, b2h);
        op[3] = make_float4(a0l, a1l, a2l, a0h);
        op[4] = make_float4(a1h, a2h, b0l, b1l);
        op[5] = make_float4(b2l, b0h, b1h, b2h);
    }

    // export per-CTA diff partials
    __syncthreads();
    for (int d = tid; d < NBLK; d += MAIN_THREADS) {
        u32 s2 = sdiff[d * 2 + 0] + sdiff[d * 2 + 1];
        g_dpart[d * MAIN_CTAS + blockIdx.x] = s2;
    }
}

// ---------------------------------------------------------------------------
// Epilogue: 2048 CTAs x 192 thr, 32 rows/CTA. Thread owns one c-column,
// summing M from the 9 slabs (L2-resident). First 87 CTAs emit stab outputs.
// ---------------------------------------------------------------------------
__global__ void __launch_bounds__(192) out_kernel(const float* __restrict__ bfin,
                                                  float* __restrict__ out) {
    __shared__ __align__(16) float s_s3[96];         // 32 rows x 3
    const int t = threadIdx.x;

    if (t < 24)
        ((float4*)s_s3)[t] = __ldg((const float4*)(g_S3 + (size_t)blockIdx.x * 96) + t);

    // ---- stability outputs ----
    const int gw = blockIdx.x * 6 + (t >> 5);
    if (blockIdx.x < 87 && gw < NBLK) {
        const int lane = t & 31;
        u64 s = 0;
        #pragma unroll
        for (int k = 0; k < 4; k++)
            s += (u64)__ldg(&g_dpart[gw * MAIN_CTAS + lane + k * 32]);
        #pragma unroll
        for (int o = 16; o; o >>= 1) s += __shfl_xor_sync(0xffffffffu, s, o);
        if (lane == 0) {
            bool first = (gw == 0) | (gw == 2) | (gw == 14) | (gw == 86);
            float val = 1.0f;
            if (!first) {
                double mean = (double)s * (1.0 / (65536.0 * 65536.0 * 3.0));
                double v = 1.0 - mean;
                val = (float)(v > 0.0 ? v : 0.0);
            }
            out[OUT_STAB_OFF + gw] = val;
        }
    }

    const int c  = t % 48;
    const int rg = t / 48;                 // 0..3
    const bool act = (c < 45);
    float4 m0 = make_float4(0.f, 0.f, 0.f, 0.f);
    float4 m1 = m0, m2 = m0, b4 = m0;
    if (act) {
        #pragma unroll
        for (int k = 0; k < 9; k++) {
            const float* Mp = g_Mpart + k * 540;
            float4 u0 = __ldg((const float4*)(Mp) + c);
            float4 u1 = __ldg((const float4*)(Mp + 180) + c);
            float4 u2 = __ldg((const float4*)(Mp + 360) + c);
            m0.x += u0.x; m0.y += u0.y; m0.z += u0.z; m0.w += u0.w;
            m1.x += u1.x; m1.y += u1.y; m1.z += u1.z; m1.w += u1.w;
            m2.x += u2.x; m2.y += u2.y; m2.z += u2.z; m2.w += u2.w;
        }
        b4 = __ldg((const float4*)bfin + c);
    }
    __syncthreads();
    const int base = rg * 8;
    #pragma unroll
    for (int it = 0; it < 8; it++) {
        int r = base + it;
        float s0 = s_s3[r * 3 + 0];
        float s1 = s_s3[r * 3 + 1];
        float s2 = s_s3[r * 3 + 2];
        if (act) {
            float4 o4;
            o4.x = fmaf(s0, m0.x, fmaf(s1, m1.x, fmaf(s2, m2.x, b4.x)));
            o4.y = fmaf(s0, m0.y, fmaf(s1, m1.y, fmaf(s2, m2.y, b4.y)));
            o4.z = fmaf(s0, m0.z, fmaf(s1, m1.z, fmaf(s2, m2.z, b4.z)));
            o4.w = fmaf(s0, m0.w, fmaf(s1, m1.w, fmaf(s2, m2.w, b4.w)));
            ((float4*)out)[((size_t)blockIdx.x * 32 + r) * 45 + c] = o4;
        }
    }
}

extern "C" void kernel_launch(void* const* d_in, const int* in_sizes, int n_in,
                              void* d_out, int out_size) {
    const float* x    = (const float*)d_in[0];
    const float* Wl   = (const float*)d_in[1];
    const float* Wi   = (const float*)d_in[2];
    const float* W1_0 = (const float*)d_in[3];
    const float* b1_0 = (const float*)d_in[4];
    const float* W2_0 = (const float*)d_in[5];
    const float* b2_0 = (const float*)d_in[6];
    const float* R0   = (const float*)d_in[7];
    const float* W1_1 = (const float*)d_in[8];
    const float* b1_1 = (const float*)d_in[9];
    const float* W2_1 = (const float*)d_in[10];
    const float* b2_1 = (const float*)d_in[11];
    const float* R1   = (const float*)d_in[12];
    const float* W1_2 = (const float*)d_in[13];
    const float* b1_2 = (const float*)d_in[14];
    const float* W2_2 = (const float*)d_in[15];
    const float* b2_2 = (const float*)d_in[16];
    const float* R2   = (const float*)d_in[17];
    const float* W1_3 = (const float*)d_in[18];
    const float* b1_3 = (const float*)d_in[19];
    const float* W2_3 = (const float*)d_in[20];
    const float* b2_3 = (const float*)d_in[21];
    const float* R3   = (const float*)d_in[22];
    const float* Wf   = (const float*)d_in[23];
    const float* bf   = (const float*)d_in[24];

    cudaFuncSetAttribute(setup_kernel, cudaFuncAttributeMaxDynamicSharedMemorySize, SETUP_SMEM);
    cudaFuncSetAttribute(main_kernel, cudaFuncAttributeMaxDynamicSharedMemorySize, MAIN_SMEM);

    setup_kernel<<<SEED_CTAS + 13, 256, SETUP_SMEM>>>(
        x, Wl, Wi, R0, R1, R2, R3, Wf,
        W1_0, b1_0, W2_0, b2_0,
        W1_1, b1_1, W2_1, b2_1,
        W1_2, b1_2, W2_2, b2_2,
        W1_3, b1_3, W2_3, b2_3);
    main_kernel<<<MAIN_CTAS, MAIN_THREADS, MAIN_SMEM>>>();
    out_kernel<<<2048, 192>>>(bf, (float*)d_out);
}